// round 2
// baseline (speedup 1.0000x reference)
#include <cuda_runtime.h>
#include <cstdint>

// ---------------------------------------------------------------------------
// SpecAugment: out = where(freq_mask[b,f] | time_mask[b,t], 0, x)
// Masks derive from jax.random.key(42) only => recompute deterministically.
//
// VARIANT 1: jax_threefry_partitionable = True  (modern JAX default)
//   split:      key_i = (lane0, lane1) of threefry(key; x0=0, x1=i)
//   bits32[i]   = lane0 ^ lane1        of threefry(key; x0=0, x1=i)
// VARIANT 0: original (pre-partitionable)
//   split(2):   counts iota(4), x0=[0,1], x1=[2,3]; keys from reshaped lanes
//   bits32 (n even): j<n/2 -> lane0 of E(j, j+n/2); else lane1 of E(j-n/2, j)
// ---------------------------------------------------------------------------
#define VARIANT_PARTITIONABLE 1

#define B_DIM 128
#define F_DIM 80
#define T_DIM 4000
#define T4    (T_DIM / 4)     // 1000 float4 per row
#define TW    (T_DIM / 32)    // 125 packed words per batch row

__device__ uint8_t  g_frow[B_DIM * F_DIM];
__device__ uint32_t g_tbits[B_DIM * TW];

struct Key { uint32_t a, b; };

__device__ __forceinline__ void tf_block(uint32_t k0, uint32_t k1,
                                         uint32_t x0, uint32_t x1,
                                         uint32_t& o0, uint32_t& o1) {
    const uint32_t ks2 = k0 ^ k1 ^ 0x1BD11BDAu;
    x0 += k0; x1 += k1;
#define RND(r) { x0 += x1; x1 = (x1 << (r)) | (x1 >> (32 - (r))); x1 ^= x0; }
    RND(13) RND(15) RND(26) RND(6)
    x0 += k1;  x1 += ks2 + 1u;
    RND(17) RND(29) RND(16) RND(24)
    x0 += ks2; x1 += k0 + 2u;
    RND(13) RND(15) RND(26) RND(6)
    x0 += k0;  x1 += k1 + 3u;
    RND(17) RND(29) RND(16) RND(24)
    x0 += k1;  x1 += ks2 + 4u;
    RND(13) RND(15) RND(26) RND(6)
    x0 += ks2; x1 += k0 + 5u;
#undef RND
    o0 = x0; o1 = x1;
}

__device__ __forceinline__ void split2(Key k, Key& ka, Key& kb) {
#if VARIANT_PARTITIONABLE
    tf_block(k.a, k.b, 0u, 0u, ka.a, ka.b);
    tf_block(k.a, k.b, 0u, 1u, kb.a, kb.b);
#else
    uint32_t e00, e01, e10, e11;
    tf_block(k.a, k.b, 0u, 2u, e00, e01);
    tf_block(k.a, k.b, 1u, 3u, e10, e11);
    ka.a = e00; ka.b = e10;   // row 0 of reshape(2,2): [out0, out1]
    kb.a = e01; kb.b = e11;   // row 1: [out2, out3]
#endif
}

// 32-bit random bits for flat index j of a draw of total size 2*half.
__device__ __forceinline__ uint32_t rbits(Key k, uint32_t j, uint32_t half) {
#if VARIANT_PARTITIONABLE
    uint32_t o0, o1;
    tf_block(k.a, k.b, 0u, j, o0, o1);
    return o0 ^ o1;
#else
    uint32_t o0, o1;
    if (j < half) { tf_block(k.a, k.b, j, j + half, o0, o1); return o0; }
    else          { tf_block(k.a, k.b, j - half, j, o0, o1); return o1; }
#endif
}

__device__ __forceinline__ float bits_to_unit_float(uint32_t ub) {
    // jax.random.uniform: bitcast((bits>>9) | 0x3f800000) - 1.0
    return __uint_as_float((ub >> 9) | 0x3f800000u) - 1.0f;
}

__global__ void __launch_bounds__(1024) setup_kernel() {
    __shared__ Key s_k1f, s_k2f, s_ksf, s_k1t, s_k2t, s_kst;
    __shared__ int s_fs[B_DIM * 2],  s_fw[B_DIM * 2];   // freq start/width
    __shared__ int s_ts[B_DIM * 10], s_tw[B_DIM * 10];  // time start/width

    const int tid = threadIdx.x;

    if (tid == 0) {
        Key key42; key42.a = 0u; key42.b = 42u;          // jax.random.key(42)
        Key kf, kt;   split2(key42, kf, kt);             // split -> (freq, time)
        Key kwf, ksf; split2(kf, kwf, ksf);              // band_mask split
        Key kwt, kst; split2(kt, kwt, kst);
        Key k1f, k2f; split2(kwf, k1f, k2f);             // _randint internal split
        Key k1t, k2t; split2(kwt, k1t, k2t);
        s_k1f = k1f; s_k2f = k2f; s_ksf = ksf;
        s_k1t = k1t; s_k2t = k2t; s_kst = kst;
    }
    __syncthreads();

    // Freq draws: shape (128, 2), span = 28 (wmax 27), multiplier = 2^32 % 28 = 4
    if (tid < B_DIM * 2) {
        uint32_t h  = rbits(s_k1f, (uint32_t)tid, 128u);
        uint32_t l  = rbits(s_k2f, (uint32_t)tid, 128u);
        uint32_t ub = rbits(s_ksf, (uint32_t)tid, 128u);
        uint32_t w  = ((h % 28u) * 4u + (l % 28u)) % 28u;
        float u  = bits_to_unit_float(ub);
        int hi   = F_DIM - (int)w;                       // max(1, 80-w), w<=27
        s_fs[tid] = (int)floorf(u * (float)hi);
        s_fw[tid] = (int)w;
    }

    // Time draws: shape (128, 10), span = 101 (wmax 100), multiplier = 2^32 % 101 = 68
    for (int j = tid; j < B_DIM * 10; j += blockDim.x) {
        uint32_t h  = rbits(s_k1t, (uint32_t)j, 640u);
        uint32_t l  = rbits(s_k2t, (uint32_t)j, 640u);
        uint32_t ub = rbits(s_kst, (uint32_t)j, 640u);
        uint32_t w  = ((h % 101u) * 68u + (l % 101u)) % 101u;
        float u  = bits_to_unit_float(ub);
        int hi   = T_DIM - (int)w;                       // max(1, 4000-w), w<=100
        s_ts[j] = (int)floorf(u * (float)hi);
        s_tw[j] = (int)w;
    }
    __syncthreads();

    // Per-(b,f) row-zero flag from the 2 freq bands.
    for (int i = tid; i < B_DIM * F_DIM; i += blockDim.x) {
        int b = i / F_DIM, f = i % F_DIM;
        int s0 = s_fs[2 * b],     e0 = s0 + s_fw[2 * b];
        int s1 = s_fs[2 * b + 1], e1 = s1 + s_fw[2 * b + 1];
        g_frow[i] = (uint8_t)(((f >= s0) & (f < e0)) | ((f >= s1) & (f < e1)));
    }

    // Bit-packed time mask: word wd covers t in [32*wd, 32*wd+32).
    for (int i = tid; i < B_DIM * TW; i += blockDim.x) {
        int b = i / TW, wd = i % TW;
        int base = wd * 32;
        uint32_t word = 0u;
#pragma unroll
        for (int m = 0; m < 10; m++) {
            int s = s_ts[b * 10 + m];
            int e = s + s_tw[b * 10 + m];
            int lo = s - base;  if (lo < 0)  lo = 0;
            int hi = e - base;  if (hi > 32) hi = 32;
            if (hi > lo) {
                uint32_t mhi = (hi >= 32) ? 0xFFFFFFFFu : ((1u << hi) - 1u);
                uint32_t mlo = ~((1u << lo) - 1u);      // lo in [0,31]
                word |= (mhi & mlo);
            }
        }
        g_tbits[i] = word;
    }
}

// Streaming apply: one float4 per thread. Grid (ceil(1000/256), 80, 128).
__global__ void __launch_bounds__(256)
apply_kernel(const float4* __restrict__ x, float4* __restrict__ out) {
    int t4 = blockIdx.x * blockDim.x + threadIdx.x;
    if (t4 >= T4) return;
    int f = blockIdx.y, b = blockIdx.z;
    int row = b * F_DIM + f;
    int idx = row * T4 + t4;

    float4 v = __ldcs(x + idx);

    uint32_t nib;
    if (g_frow[row]) {
        nib = 0xFu;
    } else {
        uint32_t word = g_tbits[b * TW + (t4 >> 3)];
        nib = (word >> ((t4 & 7) * 4)) & 0xFu;
    }
    v.x = (nib & 1u) ? 0.0f : v.x;
    v.y = (nib & 2u) ? 0.0f : v.y;
    v.z = (nib & 4u) ? 0.0f : v.z;
    v.w = (nib & 8u) ? 0.0f : v.w;

    __stcs(out + idx, v);
}

extern "C" void kernel_launch(void* const* d_in, const int* in_sizes, int n_in,
                              void* d_out, int out_size) {
    (void)in_sizes; (void)n_in; (void)out_size;
    const float4* x  = (const float4*)d_in[0];
    float4*       out = (float4*)d_out;

    setup_kernel<<<1, 1024>>>();

    dim3 grid((T4 + 255) / 256, F_DIM, B_DIM);
    apply_kernel<<<grid, 256>>>(x, out);
}

// round 3
// speedup vs baseline: 1.6264x; 1.6264x over previous
#include <cuda_runtime.h>
#include <cstdint>
#include <cmath>

// ---------------------------------------------------------------------------
// SpecAugment: out = where(freq_mask[b,f] | time_mask[b,t], 0, x)
// Masks depend only on jax.random.key(42)  =>  compute the 1280 (start,width)
// draws ON THE HOST (bit-exact threefry-2x32, partitionable variant, verified
// rel_err=0.0 in R2) and pass them as a 6.4KB __grid_constant__ kernel param.
// Device: one kernel, one block per (b,f) row, 4 float4/thread (MLP=4),
// loads SKIPPED for masked elements (freq-masked rows read nothing).
// ---------------------------------------------------------------------------

#define B_DIM 128
#define F_DIM 80
#define T_DIM 4000
#define T4    1000          // float4 per row
#define TW    125           // 32-bit mask words per batch (time dim)
#define NTHREADS 256

struct MaskParams {
    uint32_t frow[(B_DIM * F_DIM + 31) / 32];  // 320 words: bit per (b,f) row
    short ts[B_DIM * 10];                      // time band start
    short te[B_DIM * 10];                      // time band end (exclusive)
};

// ============================ device ======================================

__global__ void __launch_bounds__(NTHREADS)
apply_kernel(const float4* __restrict__ x, float4* __restrict__ out,
             const __grid_constant__ MaskParams p)
{
    const int row = blockIdx.x;            // row = b*80 + f, contiguous memory
    const int b   = row / F_DIM;
    const int tid = threadIdx.x;
    const float4* xr   = x   + (size_t)row * T4;
    float4*       orow = out + (size_t)row * T4;

    // Freq-masked row: store zeros, read nothing.
    if ((p.frow[row >> 5] >> (row & 31)) & 1u) {
        const float4 z = make_float4(0.f, 0.f, 0.f, 0.f);
#pragma unroll
        for (int i = 0; i < 4; i++) {
            int t4 = tid + i * NTHREADS;
            if (t4 < T4) __stcs(orow + t4, z);
        }
        return;
    }

    // Build this batch's packed time mask in shared (125 words, 10 bands).
    __shared__ uint32_t s_tb[TW];
    if (tid < TW) {
        const int base = tid * 32;
        uint32_t word = 0u;
#pragma unroll
        for (int m = 0; m < 10; m++) {
            int s = p.ts[b * 10 + m], e = p.te[b * 10 + m];
            int lo = s - base;  lo = lo < 0  ? 0  : lo;
            int hi = e - base;  hi = hi > 32 ? 32 : hi;
            if (hi > lo) {
                uint32_t mhi = (hi >= 32) ? 0xFFFFFFFFu : ((1u << hi) - 1u);
                word |= mhi & ~((1u << lo) - 1u);
            }
        }
        s_tb[tid] = word;
    }
    __syncthreads();

    uint32_t nib[4];
    float4   v[4];
#pragma unroll
    for (int i = 0; i < 4; i++) {
        int t4 = tid + i * NTHREADS;
        nib[i] = (t4 < T4) ? ((s_tb[t4 >> 3] >> ((t4 & 7) * 4)) & 0xFu) : 0xFu;
    }
    // Front-batched streaming loads, skipped when the whole float4 is masked.
#pragma unroll
    for (int i = 0; i < 4; i++) {
        int t4 = tid + i * NTHREADS;
        v[i] = make_float4(0.f, 0.f, 0.f, 0.f);
        if (t4 < T4 && nib[i] != 0xFu) v[i] = __ldcs(xr + t4);
    }
#pragma unroll
    for (int i = 0; i < 4; i++) {
        int t4 = tid + i * NTHREADS;
        if (t4 >= T4) continue;
        float4 r = v[i];
        r.x = (nib[i] & 1u) ? 0.f : r.x;
        r.y = (nib[i] & 2u) ? 0.f : r.y;
        r.z = (nib[i] & 4u) ? 0.f : r.z;
        r.w = (nib[i] & 8u) ? 0.f : r.w;
        __stcs(orow + t4, r);
    }
}

// ============================ host: threefry draws ========================

namespace sa_host {

struct U2 { uint32_t a, b; };

static inline U2 tf(uint32_t k0, uint32_t k1, uint32_t x0, uint32_t x1) {
    const uint32_t ks2 = k0 ^ k1 ^ 0x1BD11BDAu;
    x0 += k0; x1 += k1;
#define RND(r) { x0 += x1; x1 = (x1 << (r)) | (x1 >> (32 - (r))); x1 ^= x0; }
    RND(13) RND(15) RND(26) RND(6)
    x0 += k1;  x1 += ks2 + 1u;
    RND(17) RND(29) RND(16) RND(24)
    x0 += ks2; x1 += k0 + 2u;
    RND(13) RND(15) RND(26) RND(6)
    x0 += k0;  x1 += k1 + 3u;
    RND(17) RND(29) RND(16) RND(24)
    x0 += k1;  x1 += ks2 + 4u;
    RND(13) RND(15) RND(26) RND(6)
    x0 += ks2; x1 += k0 + 5u;
#undef RND
    return U2{x0, x1};
}

// jax_threefry_partitionable = True (verified bit-exact in R2)
static inline U2 split_a(U2 k) { return tf(k.a, k.b, 0u, 0u); }
static inline U2 split_b(U2 k) { return tf(k.a, k.b, 0u, 1u); }
static inline uint32_t rbits(U2 k, uint32_t j) {
    U2 o = tf(k.a, k.b, 0u, j);
    return o.a ^ o.b;
}

static void fill_params(MaskParams& p) {
    U2 key{0u, 42u};                       // jax.random.key(42)
    U2 kf  = split_a(key), kt  = split_b(key);
    U2 kwf = split_a(kf),  ksf = split_b(kf);
    U2 kwt = split_a(kt),  kst = split_b(kt);
    U2 k1f = split_a(kwf), k2f = split_b(kwf);
    U2 k1t = split_a(kwt), k2t = split_b(kwt);

    // Freq: (128, 2) draws, span 28, multiplier 2^32 % 28 = 4
    int fs[B_DIM * 2], fe[B_DIM * 2];
    for (int j = 0; j < B_DIM * 2; j++) {
        uint32_t h  = rbits(k1f, (uint32_t)j);
        uint32_t l  = rbits(k2f, (uint32_t)j);
        uint32_t ub = rbits(ksf, (uint32_t)j);
        uint32_t w  = ((h % 28u) * 4u + (l % 28u)) % 28u;
        float u  = (float)(ub >> 9) * (1.0f / 8388608.0f);  // exact [0,1)
        int hi   = F_DIM - (int)w;                          // max(1,80-w), w<=27
        int s    = (int)(u * (float)hi);                    // floor (u*hi >= 0)
        fs[j] = s; fe[j] = s + (int)w;
    }
    for (int i = 0; i < (int)(sizeof(p.frow) / sizeof(p.frow[0])); i++) p.frow[i] = 0u;
    for (int b = 0; b < B_DIM; b++)
        for (int f = 0; f < F_DIM; f++) {
            bool in = (f >= fs[2 * b]     && f < fe[2 * b]) ||
                      (f >= fs[2 * b + 1] && f < fe[2 * b + 1]);
            if (in) {
                int r = b * F_DIM + f;
                p.frow[r >> 5] |= 1u << (r & 31);
            }
        }

    // Time: (128, 10) draws, span 101, multiplier 2^32 % 101 = 68
    for (int j = 0; j < B_DIM * 10; j++) {
        uint32_t h  = rbits(k1t, (uint32_t)j);
        uint32_t l  = rbits(k2t, (uint32_t)j);
        uint32_t ub = rbits(kst, (uint32_t)j);
        uint32_t w  = ((h % 101u) * 68u + (l % 101u)) % 101u;
        float u  = (float)(ub >> 9) * (1.0f / 8388608.0f);
        int hi   = T_DIM - (int)w;                          // max(1,4000-w), w<=100
        int s    = (int)(u * (float)hi);
        p.ts[j] = (short)s;
        p.te[j] = (short)(s + (int)w);
    }
}

} // namespace sa_host

// ============================ launch ======================================

extern "C" void kernel_launch(void* const* d_in, const int* in_sizes, int n_in,
                              void* d_out, int out_size) {
    (void)in_sizes; (void)n_in; (void)out_size;
    const float4* x   = (const float4*)d_in[0];
    float4*       out = (float4*)d_out;

    MaskParams p;
    sa_host::fill_params(p);

    apply_kernel<<<B_DIM * F_DIM, NTHREADS>>>(x, out, p);
}